// round 7
// baseline (speedup 1.0000x reference)
#include <cuda_runtime.h>
#include <math.h>
#include <stdint.h>

#define Bb 2
#define Tt 1024
#define Cc 2048
#define Hh 32
#define Dd 64
#define BT (Bb*Tt)
#define BTC (BT*Cc)
#define NEG_INF (-1e30f)

// ---------------- scratch (device globals; no allocation) ----------------
__device__ float s_xq[BTC];
__device__ float s_xk[BTC];
__device__ float s_xv[BTC];
__device__ float s_rq[BTC];
__device__ float s_rk[BTC];
__device__ float s_rv[BTC];
__device__ float s_q[BTC];   // (B,H,T,D)
__device__ float s_k[BTC];   // (B,H,T,D)
__device__ float s_v[BTC];   // (B,H,T,D)
__device__ float s_o[BTC];   // (B,T,C)
__device__ float s_mu[BT];
__device__ float s_rs[BT];

__device__ __forceinline__ uint32_t f2tf(float f) {
    uint32_t u;
    asm("cvt.rna.tf32.f32 %0, %1;" : "=r"(u) : "f"(f));
    return u;
}

// ---------------- K1: fused shift + lora1 + mix (8 rows / block) ----------
// smem layout (floats): sx[8][2048] | partial[2][8][96] | sh[8][96]
#define PM_ROWS 8
#define PM_SX 0
#define PM_PART (PM_ROWS * Cc)
#define PM_SH (PM_PART + 2 * PM_ROWS * 96)
#define PM_SMEM ((PM_SH + PM_ROWS * 96) * 4)

__global__ __launch_bounds__(256) void k_premix(const float* __restrict__ x,
                                                const float* __restrict__ shift,
                                                const float* __restrict__ tmx,
                                                const float* __restrict__ tmr,
                                                const float* __restrict__ tmk,
                                                const float* __restrict__ tmv,
                                                const float* __restrict__ w1,
                                                const float* __restrict__ w2) {
    extern __shared__ float pm[];
    float* sx = pm + PM_SX;
    float* part = pm + PM_PART;
    float* sh = pm + PM_SH;
    int tid = threadIdx.x;
    int r0 = blockIdx.x * PM_ROWS;

    // phase A: xxx = x + (xprev - x) * tmx  -> smem
    for (int i = tid; i < PM_ROWS * Cc; i += 256) {
        int r = i >> 11, c = i & (Cc - 1);
        int bt = r0 + r;
        int t = bt & (Tt - 1);
        int b = bt >> 10;
        float xv = x[(size_t)bt * Cc + c];
        float xp = (t == 0) ? shift[b * Cc + c] : x[(size_t)(bt - 1) * Cc + c];
        sx[r * Cc + c] = xv + (xp - xv) * tmx[c];
    }
    __syncthreads();

    // phase B: h = tanh(xxx @ w1), 2-way K split over thread groups
    if (tid < 192) {
        int g = tid / 96, j = tid - g * 96;
        int c0 = g * (Cc / 2);
        float a[PM_ROWS];
#pragma unroll
        for (int r = 0; r < PM_ROWS; r++) a[r] = 0.f;
        for (int c = c0; c < c0 + Cc / 2; c += 4) {
            float w0 = w1[(size_t)(c + 0) * 96 + j];
            float w1v = w1[(size_t)(c + 1) * 96 + j];
            float w2v = w1[(size_t)(c + 2) * 96 + j];
            float w3 = w1[(size_t)(c + 3) * 96 + j];
#pragma unroll
            for (int r = 0; r < PM_ROWS; r++) {
                a[r] += sx[r * Cc + c] * w0 + sx[r * Cc + c + 1] * w1v +
                        sx[r * Cc + c + 2] * w2v + sx[r * Cc + c + 3] * w3;
            }
        }
#pragma unroll
        for (int r = 0; r < PM_ROWS; r++) part[(g * PM_ROWS + r) * 96 + j] = a[r];
    }
    __syncthreads();
    if (tid < 96) {
#pragma unroll
        for (int r = 0; r < PM_ROWS; r++)
            sh[r * 96 + tid] = tanhf(part[r * 96 + tid] + part[(PM_ROWS + r) * 96 + tid]);
    }
    __syncthreads();

    // phase C: m = h @ w2 per l; write xq/xk/xv
    for (int c = tid; c < Cc; c += 256) {
        float mr[PM_ROWS], mk[PM_ROWS], mv[PM_ROWS];
#pragma unroll
        for (int r = 0; r < PM_ROWS; r++) { mr[r] = 0.f; mk[r] = 0.f; mv[r] = 0.f; }
#pragma unroll 8
        for (int i = 0; i < 32; i++) {
            float wr = w2[(size_t)i * Cc + c];
            float wk = w2[(size_t)(32 + i) * Cc + c];
            float wv = w2[(size_t)(64 + i) * Cc + c];
#pragma unroll
            for (int r = 0; r < PM_ROWS; r++) {
                mr[r] += sh[r * 96 + i] * wr;
                mk[r] += sh[r * 96 + 32 + i] * wk;
                mv[r] += sh[r * 96 + 64 + i] * wv;
            }
        }
        float tr = tmr[c], tk = tmk[c], tv = tmv[c];
#pragma unroll
        for (int r = 0; r < PM_ROWS; r++) {
            int bt = r0 + r;
            int t = bt & (Tt - 1);
            int b = bt >> 10;
            size_t idx = (size_t)bt * Cc + c;
            float xv = x[idx];
            float xp = (t == 0) ? shift[b * Cc + c] : x[idx - Cc];
            float dx = xp - xv;
            s_xq[idx] = xv + dx * (tr + mr[r]);
            s_xk[idx] = xv + dx * (tk + mk[r]);
            s_xv[idx] = xv + dx * (tv + mv[r]);
        }
    }
}

// ---------------- TF32 tensor-core GEMM (round-2 core): 128x128, BK=32 ----
#define AS_STRIDE 36
#define BS_STRIDE 136

template <bool LNA>
__device__ __forceinline__ void gemm_tf32(const float* __restrict__ A,
                                          const float* __restrict__ W,
                                          float* __restrict__ Co,
                                          const float* __restrict__ mu,
                                          const float* __restrict__ rs,
                                          const float* __restrict__ lg,
                                          const float* __restrict__ lb) {
    __shared__ uint32_t As[128 * AS_STRIDE];   // [m][k] padded
    __shared__ uint32_t Bs[32 * BS_STRIDE];    // [k][n] padded
    int tid = threadIdx.x;
    int m0 = blockIdx.y * 128, n0 = blockIdx.x * 128;
    int warp = tid >> 5, lane = tid & 31;
    int wm = (warp & 3) * 32;
    int wn = (warp >> 2) * 64;
    int gid = lane >> 2, tig = lane & 3;

    int ar = tid >> 1, ac = (tid & 1) * 4;     // A: row ar, cols ac (k)
    int br = tid >> 5, bc = (tid & 31) * 4;    // B: row br (k), cols bc
    const float* Ap = A + (size_t)(m0 + ar) * Cc + ac;
    const float* Wp = W + (size_t)br * Cc + n0 + bc;

    float muv = 0.f, rsv = 0.f;
    if (LNA) { muv = mu[m0 + ar]; rsv = rs[m0 + ar]; }

    float4 av = *(const float4*)(Ap);
    float4 bv = *(const float4*)(Wp);
    float4 ga, ba;
    if (LNA) { ga = *(const float4*)(lg + ac); ba = *(const float4*)(lb + ac); }

    float acc[2][8][4];
#pragma unroll
    for (int mt = 0; mt < 2; mt++)
#pragma unroll
        for (int nt = 0; nt < 8; nt++)
#pragma unroll
            for (int i = 0; i < 4; i++) acc[mt][nt][i] = 0.f;

    for (int k0 = 0; k0 < Cc; k0 += 8) {
        if (LNA) {
            av.x = (av.x - muv) * rsv * ga.x + ba.x;
            av.y = (av.y - muv) * rsv * ga.y + ba.y;
            av.z = (av.z - muv) * rsv * ga.z + ba.z;
            av.w = (av.w - muv) * rsv * ga.w + ba.w;
        }
        As[ar * AS_STRIDE + ac + 0] = f2tf(av.x);
        As[ar * AS_STRIDE + ac + 1] = f2tf(av.y);
        As[ar * AS_STRIDE + ac + 2] = f2tf(av.z);
        As[ar * AS_STRIDE + ac + 3] = f2tf(av.w);
        // NOTE: round-2 layout had As[k][m]; here store [m][k] padded (same as
        // fragment indexing below which reads As[(row)*AS_STRIDE + k]).
        uint32_t* sb = &Bs[br * BS_STRIDE + bc];
        sb[0] = f2tf(bv.x); sb[1] = f2tf(bv.y);
        sb[2] = f2tf(bv.z); sb[3] = f2tf(bv.w);
        __syncthreads();
        if (k0 + 8 < Cc) {
            av = *(const float4*)(Ap + (k0 + 8));
            bv = *(const float4*)(Wp + (size_t)(k0 + 8) * Cc);
            if (LNA) {
                ga = *(const float4*)(lg + k0 + 8 + ac);
                ba = *(const float4*)(lb + k0 + 8 + ac);
            }
        }
        // K-slab of 8 in smem; 1 kk step
        {
            uint32_t af[2][4], bf[8][2];
#pragma unroll
            for (int mt = 0; mt < 2; mt++) {
                const uint32_t* ap = &As[(wm + mt * 16 + gid) * AS_STRIDE + tig];
                af[mt][0] = ap[0];
                af[mt][1] = ap[8 * AS_STRIDE];
                af[mt][2] = ap[4];
                af[mt][3] = ap[8 * AS_STRIDE + 4];
            }
#pragma unroll
            for (int nt = 0; nt < 8; nt++) {
                const uint32_t* bp = &Bs[tig * BS_STRIDE + wn + nt * 8 + gid];
                bf[nt][0] = bp[0];
                bf[nt][1] = bp[4 * BS_STRIDE];
            }
#pragma unroll
            for (int mt = 0; mt < 2; mt++)
#pragma unroll
                for (int nt = 0; nt < 8; nt++) {
                    asm volatile(
                        "mma.sync.aligned.m16n8k8.row.col.f32.tf32.tf32.f32 "
                        "{%0,%1,%2,%3}, {%4,%5,%6,%7}, {%8,%9}, {%0,%1,%2,%3};"
                        : "+f"(acc[mt][nt][0]), "+f"(acc[mt][nt][1]),
                          "+f"(acc[mt][nt][2]), "+f"(acc[mt][nt][3])
                        : "r"(af[mt][0]), "r"(af[mt][1]), "r"(af[mt][2]), "r"(af[mt][3]),
                          "r"(bf[nt][0]), "r"(bf[nt][1]));
                }
        }
        __syncthreads();
    }
#pragma unroll
    for (int mt = 0; mt < 2; mt++)
#pragma unroll
        for (int nt = 0; nt < 8; nt++) {
            int row = m0 + wm + mt * 16 + gid;
            int col = n0 + wn + nt * 8 + tig * 2;
            *(float2*)&Co[(size_t)row * Cc + col] = make_float2(acc[mt][nt][0], acc[mt][nt][1]);
            *(float2*)&Co[(size_t)(row + 8) * Cc + col] = make_float2(acc[mt][nt][2], acc[mt][nt][3]);
        }
}

__global__ __launch_bounds__(256) void k_gemm_qkv(const float* __restrict__ Wq,
                                                  const float* __restrict__ Wk,
                                                  const float* __restrict__ Wv) {
    const float* A = (blockIdx.z == 0) ? s_xq : (blockIdx.z == 1) ? s_xk : s_xv;
    const float* W = (blockIdx.z == 0) ? Wq : (blockIdx.z == 1) ? Wk : Wv;
    float* Co = (blockIdx.z == 0) ? s_rq : (blockIdx.z == 1) ? s_rk : s_rv;
    gemm_tf32<false>(A, W, Co, nullptr, nullptr, nullptr, nullptr);
}

__global__ __launch_bounds__(256) void k_gemm_out(const float* __restrict__ Wo,
                                                  const float* __restrict__ gx,
                                                  const float* __restrict__ bx,
                                                  float* __restrict__ out) {
    gemm_tf32<true>(s_o, Wo, out, s_mu, s_rs, gx, bx);
}

// ---------------- K-lnstats: per-row mean/rstd of s_o ----------------
__global__ __launch_bounds__(256) void k_lnstats() {
    int row = blockIdx.x * 8 + (threadIdx.x >> 5);
    int lane = threadIdx.x & 31;
    const float* p = s_o + (size_t)row * Cc;
    float s = 0.f, q = 0.f;
    for (int c = lane * 4; c < Cc; c += 128) {
        float4 v = *(const float4*)(p + c);
        s += v.x + v.y + v.z + v.w;
        q += v.x * v.x + v.y * v.y + v.z * v.z + v.w * v.w;
    }
#pragma unroll
    for (int o = 16; o; o >>= 1) {
        s += __shfl_xor_sync(0xffffffffu, s, o);
        q += __shfl_xor_sync(0xffffffffu, q, o);
    }
    if (lane == 0) {
        float mu = s * (1.f / Cc);
        float var = q * (1.f / Cc) - mu * mu;
        s_mu[row] = mu;
        s_rs[row] = rsqrtf(var + 1e-5f);
    }
}

// ---------------- K5: LayerNorm (+RoPE for q,k), write (B,H,T,D) ----------
__global__ __launch_bounds__(256) void k_lnrope(const float* __restrict__ gr, const float* __restrict__ br,
                                                const float* __restrict__ gk, const float* __restrict__ bk,
                                                const float* __restrict__ gv, const float* __restrict__ bv,
                                                const float* __restrict__ cosp, const float* __restrict__ sinp) {
    int mode = blockIdx.y;
    const float* raw = (mode == 0) ? s_rq : (mode == 1) ? s_rk : s_rv;
    float* outp = (mode == 0) ? s_q : (mode == 1) ? s_k : s_v;
    const float* gp = (mode == 0) ? gr : (mode == 1) ? gk : gv;
    const float* bp = (mode == 0) ? br : (mode == 1) ? bk : bv;
    int bt = blockIdx.x;
    int t = bt & (Tt - 1);
    int b = bt >> 10;
    __shared__ float srow[Cc];
    __shared__ float red[16];
    float ls = 0.f, lq = 0.f;
    for (int c = threadIdx.x; c < Cc; c += 256) {
        float v = raw[(size_t)bt * Cc + c];
        srow[c] = v;
        ls += v;
        lq += v * v;
    }
#pragma unroll
    for (int o = 16; o; o >>= 1) {
        ls += __shfl_xor_sync(0xffffffffu, ls, o);
        lq += __shfl_xor_sync(0xffffffffu, lq, o);
    }
    if ((threadIdx.x & 31) == 0) {
        red[threadIdx.x >> 5] = ls;
        red[8 + (threadIdx.x >> 5)] = lq;
    }
    __syncthreads();
    float sum = 0.f, sq = 0.f;
#pragma unroll
    for (int i = 0; i < 8; i++) {
        sum += red[i];
        sq += red[8 + i];
    }
    float mu = sum * (1.f / Cc);
    float var = sq * (1.f / Cc) - mu * mu;
    float rstd = rsqrtf(var + 1e-5f);
    for (int c = threadIdx.x; c < Cc; c += 256)
        srow[c] = (srow[c] - mu) * rstd * gp[c] + bp[c];
    __syncthreads();
    for (int c = threadIdx.x; c < Cc; c += 256) {
        int hh = c >> 6, d = c & 63;
        float y;
        if (mode < 2) {
            if (d < 32)
                y = srow[c] * cosp[t * 32 + d] - srow[c + 32] * sinp[t * 32 + d];
            else
                y = srow[c - 32] * sinp[t * 32 + d - 32] + srow[c] * cosp[t * 32 + d - 32];
        } else {
            y = srow[c];
        }
        outp[((size_t)(b * Hh + hh) * Tt + t) * Dd + d] = y;
    }
}

// ---------------- K6: tensor-core causal flash attention ------------------
#define SD 68
#define SDV 72
#define FL_TILE (64 * SD)
#define FL_SMEM ((5 * FL_TILE + 64 * SDV + 256) * 4)

__global__ __launch_bounds__(256) void k_flash() {
    extern __shared__ uint32_t fsm[];
    uint32_t* Qh = fsm;
    uint32_t* Ql = Qh + FL_TILE;
    uint32_t* Kh = Ql + FL_TILE;
    uint32_t* Kl = Kh + FL_TILE;
    uint32_t* Pt = Kl + FL_TILE;
    uint32_t* Vt = Pt + FL_TILE;
    float* red = (float*)(Vt + 64 * SDV);

    int tid = threadIdx.x;
    int warp = tid >> 5, lane = tid & 31;
    int gid = lane >> 2, tig = lane & 3;
    int qw = (warp & 3) * 16;
    int sh = warp >> 2;
    int sb = sh * 32;

    int q0 = blockIdx.x * 64;
    int bh = blockIdx.y;
    int b = bh >> 5, h = bh & 31;
    const float* qp = s_q + (size_t)bh * Tt * Dd;
    const float* kp = s_k + (size_t)bh * Tt * Dd;
    const float* vp = s_v + (size_t)bh * Tt * Dd;

#pragma unroll
    for (int it = 0; it < 4; it++) {
        int lin = tid + it * 256;
        int row = lin >> 4, c4 = (lin & 15) * 4;
        float4 v = *(const float4*)(qp + (size_t)(q0 + row) * 64 + c4);
        v.x *= 0.125f; v.y *= 0.125f; v.z *= 0.125f; v.w *= 0.125f;
        uint4 hi = make_uint4(f2tf(v.x), f2tf(v.y), f2tf(v.z), f2tf(v.w));
        uint4 lo = make_uint4(f2tf(v.x - __uint_as_float(hi.x)),
                              f2tf(v.y - __uint_as_float(hi.y)),
                              f2tf(v.z - __uint_as_float(hi.z)),
                              f2tf(v.w - __uint_as_float(hi.w)));
        *(uint4*)&Qh[row * SD + c4] = hi;
        *(uint4*)&Ql[row * SD + c4] = lo;
    }

    float oacc[4][4];
#pragma unroll
    for (int nt = 0; nt < 4; nt++)
#pragma unroll
        for (int i = 0; i < 4; i++) oacc[nt][i] = 0.f;
    float m0 = NEG_INF, m1 = NEG_INF, l0 = 0.f, l1 = 0.f;
    int row0 = q0 + qw + gid;
    int row1 = row0 + 8;

    for (int s0 = 0; s0 <= q0; s0 += 64) {
        __syncthreads();
#pragma unroll
        for (int it = 0; it < 4; it++) {
            int lin = tid + it * 256;
            int row = lin >> 4, c4 = (lin & 15) * 4;
            float4 kv = *(const float4*)(kp + (size_t)(s0 + row) * 64 + c4);
            uint4 hi = make_uint4(f2tf(kv.x), f2tf(kv.y), f2tf(kv.z), f2tf(kv.w));
            uint4 lo = make_uint4(f2tf(kv.x - __uint_as_float(hi.x)),
                                  f2tf(kv.y - __uint_as_float(hi.y)),
                                  f2tf(kv.z - __uint_as_float(hi.z)),
                                  f2tf(kv.w - __uint_as_float(hi.w)));
            *(uint4*)&Kh[row * SD + c4] = hi;
            *(uint4*)&Kl[row * SD + c4] = lo;
            float4 vv = *(const float4*)(vp + (size_t)(s0 + row) * 64 + c4);
            uint4 vt = make_uint4(f2tf(vv.x), f2tf(vv.y), f2tf(vv.z), f2tf(vv.w));
            *(uint4*)&Vt[row * SDV + c4] = vt;
        }
        __syncthreads();

        float sacc[4][4];
#pragma unroll
        for (int nt = 0; nt < 4; nt++)
#pragma unroll
            for (int i = 0; i < 4; i++) sacc[nt][i] = 0.f;
#pragma unroll
        for (int kk = 0; kk < 8; kk++) {
            int kb = kk * 8;
            uint32_t ah[4], al[4];
            const uint32_t* aph = &Qh[(qw + gid) * SD + kb + tig];
            const uint32_t* apl = &Ql[(qw + gid) * SD + kb + tig];
            ah[0] = aph[0]; ah[1] = aph[8 * SD]; ah[2] = aph[4]; ah[3] = aph[8 * SD + 4];
            al[0] = apl[0]; al[1] = apl[8 * SD]; al[2] = apl[4]; al[3] = apl[8 * SD + 4];
#pragma unroll
            for (int nt = 0; nt < 4; nt++) {
                int n0 = sb + nt * 8;
                const uint32_t* bph = &Kh[(n0 + gid) * SD + kb + tig];
                const uint32_t* bpl = &Kl[(n0 + gid) * SD + kb + tig];
                uint32_t bh0 = bph[0], bh1 = bph[4];
                uint32_t bl0 = bpl[0], bl1 = bpl[4];
#define MMA_S(Areg, B0, B1)                                                   \
    asm volatile(                                                             \
        "mma.sync.aligned.m16n8k8.row.col.f32.tf32.tf32.f32 "                 \
        "{%0,%1,%2,%3}, {%4,%5,%6,%7}, {%8,%9}, {%0,%1,%2,%3};"               \
        : "+f"(sacc[nt][0]), "+f"(sacc[nt][1]), "+f"(sacc[nt][2]),            \
          "+f"(sacc[nt][3])                                                   \
        : "r"(Areg[0]), "r"(Areg[1]), "r"(Areg[2]), "r"(Areg[3]), "r"(B0),    \
          "r"(B1));
                MMA_S(ah, bh0, bh1)
                MMA_S(ah, bl0, bl1)
                MMA_S(al, bh0, bh1)
#undef MMA_S
            }
        }

        float mt0 = NEG_INF, mt1 = NEG_INF;
#pragma unroll
        for (int nt = 0; nt < 4; nt++) {
            int cbase = s0 + sb + nt * 8 + 2 * tig;
            sacc[nt][0] = (cbase <= row0) ? sacc[nt][0] : NEG_INF;
            sacc[nt][1] = (cbase + 1 <= row0) ? sacc[nt][1] : NEG_INF;
            sacc[nt][2] = (cbase <= row1) ? sacc[nt][2] : NEG_INF;
            sacc[nt][3] = (cbase + 1 <= row1) ? sacc[nt][3] : NEG_INF;
            mt0 = fmaxf(mt0, fmaxf(sacc[nt][0], sacc[nt][1]));
            mt1 = fmaxf(mt1, fmaxf(sacc[nt][2], sacc[nt][3]));
        }
        mt0 = fmaxf(mt0, __shfl_xor_sync(0xffffffffu, mt0, 1));
        mt0 = fmaxf(mt0, __shfl_xor_sync(0xffffffffu, mt0, 2));
        mt1 = fmaxf(mt1, __shfl_xor_sync(0xffffffffu, mt1, 1));
        mt1 = fmaxf(mt1, __shfl_xor_sync(0xffffffffu, mt1, 2));
        if (tig == 0) {
            red[sh * 64 + qw + gid] = mt0;
            red[sh * 64 + qw + gid + 8] = mt1;
        }
        __syncthreads();
        float mn0 = fmaxf(m0, fmaxf(red[qw + gid], red[64 + qw + gid]));
        float mn1 = fmaxf(m1, fmaxf(red[qw + gid + 8], red[64 + qw + gid + 8]));
        float corr0 = __expf(m0 - mn0);
        float corr1 = __expf(m1 - mn1);
        m0 = mn0; m1 = mn1;

        float ls0 = 0.f, ls1 = 0.f;
#pragma unroll
        for (int nt = 0; nt < 4; nt++) {
            int cb = sb + nt * 8 + 2 * tig;
            float p0 = __expf(sacc[nt][0] - mn0);
            float p1 = __expf(sacc[nt][1] - mn0);
            float p2 = __expf(sacc[nt][2] - mn1);
            float p3 = __expf(sacc[nt][3] - mn1);
            ls0 += p0 + p1;
            ls1 += p2 + p3;
            Pt[(qw + gid) * SD + cb] = f2tf(p0);
            Pt[(qw + gid) * SD + cb + 1] = f2tf(p1);
            Pt[(qw + gid + 8) * SD + cb] = f2tf(p2);
            Pt[(qw + gid + 8) * SD + cb + 1] = f2tf(p3);
        }
        ls0 += __shfl_xor_sync(0xffffffffu, ls0, 1);
        ls0 += __shfl_xor_sync(0xffffffffu, ls0, 2);
        ls1 += __shfl_xor_sync(0xffffffffu, ls1, 1);
        ls1 += __shfl_xor_sync(0xffffffffu, ls1, 2);
        if (tig == 0) {
            red[128 + sh * 64 + qw + gid] = ls0;
            red[128 + sh * 64 + qw + gid + 8] = ls1;
        }
        __syncthreads();
        l0 = l0 * corr0 + red[128 + qw + gid] + red[128 + 64 + qw + gid];
        l1 = l1 * corr1 + red[128 + qw + gid + 8] + red[128 + 64 + qw + gid + 8];

#pragma unroll
        for (int nt = 0; nt < 4; nt++) {
            oacc[nt][0] *= corr0;
            oacc[nt][1] *= corr0;
            oacc[nt][2] *= corr1;
            oacc[nt][3] *= corr1;
        }
#pragma unroll
        for (int kk = 0; kk < 8; kk++) {
            int kb = kk * 8;
            uint32_t af[4];
            const uint32_t* ap = &Pt[(qw + gid) * SD + kb + tig];
            af[0] = ap[0]; af[1] = ap[8 * SD]; af[2] = ap[4]; af[3] = ap[8 * SD + 4];
#pragma unroll
            for (int nt = 0; nt < 4; nt++) {
                int n0 = sb + nt * 8;
                uint32_t b0 = Vt[(kb + tig) * SDV + n0 + gid];
                uint32_t b1 = Vt[(kb + tig + 4) * SDV + n0 + gid];
                asm volatile(
                    "mma.sync.aligned.m16n8k8.row.col.f32.tf32.tf32.f32 "
                    "{%0,%1,%2,%3}, {%4,%5,%6,%7}, {%8,%9}, {%0,%1,%2,%3};"
                    : "+f"(oacc[nt][0]), "+f"(oacc[nt][1]), "+f"(oacc[nt][2]),
                      "+f"(oacc[nt][3])
                    : "r"(af[0]), "r"(af[1]), "r"(af[2]), "r"(af[3]),
                      "r"(b0), "r"(b1));
            }
        }
    }

    float inv0 = 1.f / l0, inv1 = 1.f / l1;
#pragma unroll
    for (int nt = 0; nt < 4; nt++) {
        int col = h * 64 + sb + nt * 8 + 2 * tig;
        *(float2*)&s_o[(size_t)(b * Tt + row0) * Cc + col] =
            make_float2(oacc[nt][0] * inv0, oacc[nt][1] * inv0);
        *(float2*)&s_o[(size_t)(b * Tt + row1) * Cc + col] =
            make_float2(oacc[nt][2] * inv1, oacc[nt][3] * inv1);
    }
}

// ---------------- launch ----------------
extern "C" void kernel_launch(void* const* d_in, const int* in_sizes, int n_in,
                              void* d_out, int out_size) {
    const float* x = (const float*)d_in[0];
    const float* shift = (const float*)d_in[1];
    const float* tmx = (const float*)d_in[2];
    const float* tmr = (const float*)d_in[3];
    const float* tmk = (const float*)d_in[4];
    const float* tmv = (const float*)d_in[5];
    const float* w1 = (const float*)d_in[6];
    const float* w2 = (const float*)d_in[7];
    const float* Wq = (const float*)d_in[8];
    const float* Wk = (const float*)d_in[9];
    const float* Wv = (const float*)d_in[10];
    const float* Wo = (const float*)d_in[11];
    const float* gr = (const float*)d_in[12];
    const float* br = (const float*)d_in[13];
    const float* gk = (const float*)d_in[14];
    const float* bk = (const float*)d_in[15];
    const float* gv = (const float*)d_in[16];
    const float* bv = (const float*)d_in[17];
    const float* gx = (const float*)d_in[18];
    const float* bx = (const float*)d_in[19];
    const float* cosp = (const float*)d_in[20];
    const float* sinp = (const float*)d_in[21];
    float* out = (float*)d_out;

    cudaFuncSetAttribute(k_premix, cudaFuncAttributeMaxDynamicSharedMemorySize, PM_SMEM);
    cudaFuncSetAttribute(k_flash, cudaFuncAttributeMaxDynamicSharedMemorySize, FL_SMEM);

    k_premix<<<BT / PM_ROWS, 256, PM_SMEM>>>(x, shift, tmx, tmr, tmk, tmv, w1, w2);
    k_gemm_qkv<<<dim3(16, 16, 3), 256>>>(Wq, Wk, Wv);
    k_lnrope<<<dim3(BT, 3), 256>>>(gr, br, gk, bk, gv, bv, cosp, sinp);
    k_flash<<<dim3(16, 64), 256, FL_SMEM>>>();
    k_lnstats<<<BT / 8, 256>>>();
    k_gemm_out<<<dim3(16, 16), 256>>>(Wo, gx, bx, out);
}

// round 8
// speedup vs baseline: 1.1549x; 1.1549x over previous
#include <cuda_runtime.h>
#include <math.h>
#include <stdint.h>

#define Bb 2
#define Tt 1024
#define Cc 2048
#define Hh 32
#define Dd 64
#define BT (Bb*Tt)
#define BTC (BT*Cc)
#define NEG_INF (-1e30f)

// ---------------- scratch (device globals; no allocation) ----------------
__device__ float s_xq[BTC];
__device__ float s_xk[BTC];
__device__ float s_xv[BTC];
__device__ float s_rq[BTC];
__device__ float s_rk[BTC];
__device__ float s_rv[BTC];
__device__ float s_q[BTC];   // (B,H,T,D)
__device__ float s_k[BTC];   // (B,H,T,D)
__device__ float s_v[BTC];   // (B,H,T,D)
__device__ float s_o[BTC];   // (B,T,C)
__device__ float s_mu[BT];
__device__ float s_rs[BT];

__device__ __forceinline__ uint32_t f2tf(float f) {
    uint32_t u;
    asm("cvt.rna.tf32.f32 %0, %1;" : "=r"(u) : "f"(f));
    return u;
}

// ---------------- K1: fused shift + lora1 + mix (8 rows / block) ----------
#define PM_ROWS 8
#define PM_SX 0
#define PM_PART (PM_ROWS * Cc)
#define PM_SH (PM_PART + 2 * PM_ROWS * 96)
#define PM_SMEM ((PM_SH + PM_ROWS * 96) * 4)

__global__ __launch_bounds__(256) void k_premix(const float* __restrict__ x,
                                                const float* __restrict__ shift,
                                                const float* __restrict__ tmx,
                                                const float* __restrict__ tmr,
                                                const float* __restrict__ tmk,
                                                const float* __restrict__ tmv,
                                                const float* __restrict__ w1,
                                                const float* __restrict__ w2) {
    extern __shared__ float pm[];
    float* sx = pm + PM_SX;
    float* part = pm + PM_PART;
    float* sh = pm + PM_SH;
    int tid = threadIdx.x;
    int r0 = blockIdx.x * PM_ROWS;

    for (int i = tid; i < PM_ROWS * Cc; i += 256) {
        int r = i >> 11, c = i & (Cc - 1);
        int bt = r0 + r;
        int t = bt & (Tt - 1);
        int b = bt >> 10;
        float xv = x[(size_t)bt * Cc + c];
        float xp = (t == 0) ? shift[b * Cc + c] : x[(size_t)(bt - 1) * Cc + c];
        sx[r * Cc + c] = xv + (xp - xv) * tmx[c];
    }
    __syncthreads();

    if (tid < 192) {
        int g = tid / 96, j = tid - g * 96;
        int c0 = g * (Cc / 2);
        float a[PM_ROWS];
#pragma unroll
        for (int r = 0; r < PM_ROWS; r++) a[r] = 0.f;
        for (int c = c0; c < c0 + Cc / 2; c += 4) {
            float w0 = w1[(size_t)(c + 0) * 96 + j];
            float w1v = w1[(size_t)(c + 1) * 96 + j];
            float w2v = w1[(size_t)(c + 2) * 96 + j];
            float w3 = w1[(size_t)(c + 3) * 96 + j];
#pragma unroll
            for (int r = 0; r < PM_ROWS; r++) {
                a[r] += sx[r * Cc + c] * w0 + sx[r * Cc + c + 1] * w1v +
                        sx[r * Cc + c + 2] * w2v + sx[r * Cc + c + 3] * w3;
            }
        }
#pragma unroll
        for (int r = 0; r < PM_ROWS; r++) part[(g * PM_ROWS + r) * 96 + j] = a[r];
    }
    __syncthreads();
    if (tid < 96) {
#pragma unroll
        for (int r = 0; r < PM_ROWS; r++)
            sh[r * 96 + tid] = tanhf(part[r * 96 + tid] + part[(PM_ROWS + r) * 96 + tid]);
    }
    __syncthreads();

    for (int c = tid; c < Cc; c += 256) {
        float mr[PM_ROWS], mk[PM_ROWS], mv[PM_ROWS];
#pragma unroll
        for (int r = 0; r < PM_ROWS; r++) { mr[r] = 0.f; mk[r] = 0.f; mv[r] = 0.f; }
#pragma unroll 8
        for (int i = 0; i < 32; i++) {
            float wr = w2[(size_t)i * Cc + c];
            float wk = w2[(size_t)(32 + i) * Cc + c];
            float wv = w2[(size_t)(64 + i) * Cc + c];
#pragma unroll
            for (int r = 0; r < PM_ROWS; r++) {
                mr[r] += sh[r * 96 + i] * wr;
                mk[r] += sh[r * 96 + 32 + i] * wk;
                mv[r] += sh[r * 96 + 64 + i] * wv;
            }
        }
        float tr = tmr[c], tk = tmk[c], tv = tmv[c];
#pragma unroll
        for (int r = 0; r < PM_ROWS; r++) {
            int bt = r0 + r;
            int t = bt & (Tt - 1);
            int b = bt >> 10;
            size_t idx = (size_t)bt * Cc + c;
            float xv = x[idx];
            float xp = (t == 0) ? shift[b * Cc + c] : x[idx - Cc];
            float dx = xp - xv;
            s_xq[idx] = xv + dx * (tr + mr[r]);
            s_xk[idx] = xv + dx * (tk + mk[r]);
            s_xv[idx] = xv + dx * (tv + mv[r]);
        }
    }
}

// ---------------- TF32 tensor-core GEMM: 128x128 tile, BK=32 (round-2) ----
#define AS_STRIDE 36
#define BS_STRIDE 136

template <bool LNA>
__device__ __forceinline__ void gemm_tf32(const float* __restrict__ A,
                                          const float* __restrict__ W,
                                          float* __restrict__ Co,
                                          const float* __restrict__ mu,
                                          const float* __restrict__ rs,
                                          const float* __restrict__ lg,
                                          const float* __restrict__ lb) {
    __shared__ uint32_t As[128 * AS_STRIDE];   // [m][k] padded
    __shared__ uint32_t Bs[32 * BS_STRIDE];    // [k][n] padded
    int tid = threadIdx.x;
    int m0 = blockIdx.y * 128, n0 = blockIdx.x * 128;
    int warp = tid >> 5, lane = tid & 31;
    int wm = (warp & 3) * 32;
    int wn = (warp >> 2) * 64;
    int gid = lane >> 2, tig = lane & 3;

    int ar = tid >> 3, ac = (tid & 7) * 4;    // A: rows ar+32i, k-cols ac
    int br = tid >> 5, bc = (tid & 31) * 4;   // B: k-rows br+8i, cols bc
    const float* Ap = A + (size_t)(m0 + ar) * Cc + ac;
    const float* Wp = W + (size_t)br * Cc + n0 + bc;

    float muv[4], rsv[4];
    if (LNA) {
#pragma unroll
        for (int i = 0; i < 4; i++) {
            muv[i] = mu[m0 + ar + 32 * i];
            rsv[i] = rs[m0 + ar + 32 * i];
        }
    }

    float4 pa[4], pb[4], ga, ba;
#pragma unroll
    for (int i = 0; i < 4; i++) {
        pa[i] = *(const float4*)(Ap + (size_t)i * 32 * Cc);
        pb[i] = *(const float4*)(Wp + (size_t)i * 8 * Cc);
    }
    if (LNA) {
        ga = *(const float4*)(lg + ac);
        ba = *(const float4*)(lb + ac);
    }

    float acc[2][8][4];
#pragma unroll
    for (int mt = 0; mt < 2; mt++)
#pragma unroll
        for (int nt = 0; nt < 8; nt++)
#pragma unroll
            for (int i = 0; i < 4; i++) acc[mt][nt][i] = 0.f;

    for (int k0 = 0; k0 < Cc; k0 += 32) {
#pragma unroll
        for (int i = 0; i < 4; i++) {
            float4 v = pa[i];
            if (LNA) {
                float rg = rsv[i];
                float mv = muv[i];
                v.x = (v.x - mv) * rg * ga.x + ba.x;
                v.y = (v.y - mv) * rg * ga.y + ba.y;
                v.z = (v.z - mv) * rg * ga.z + ba.z;
                v.w = (v.w - mv) * rg * ga.w + ba.w;
            }
            uint32_t* sa = &As[(ar + 32 * i) * AS_STRIDE + ac];
            sa[0] = f2tf(v.x); sa[1] = f2tf(v.y);
            sa[2] = f2tf(v.z); sa[3] = f2tf(v.w);
            uint32_t* sb = &Bs[(br + 8 * i) * BS_STRIDE + bc];
            sb[0] = f2tf(pb[i].x); sb[1] = f2tf(pb[i].y);
            sb[2] = f2tf(pb[i].z); sb[3] = f2tf(pb[i].w);
        }
        __syncthreads();
        if (k0 + 32 < Cc) {
            Ap += 32;
            Wp += (size_t)32 * Cc;
#pragma unroll
            for (int i = 0; i < 4; i++) {
                pa[i] = *(const float4*)(Ap + (size_t)i * 32 * Cc);
                pb[i] = *(const float4*)(Wp + (size_t)i * 8 * Cc);
            }
            if (LNA) {
                ga = *(const float4*)(lg + k0 + 32 + ac);
                ba = *(const float4*)(lb + k0 + 32 + ac);
            }
        }
#pragma unroll
        for (int kk = 0; kk < 4; kk++) {
            int kb = kk * 8;
            uint32_t af[2][4], bf[8][2];
#pragma unroll
            for (int mt = 0; mt < 2; mt++) {
                const uint32_t* ap = &As[(wm + mt * 16 + gid) * AS_STRIDE + kb + tig];
                af[mt][0] = ap[0];
                af[mt][1] = ap[8 * AS_STRIDE];
                af[mt][2] = ap[4];
                af[mt][3] = ap[8 * AS_STRIDE + 4];
            }
#pragma unroll
            for (int nt = 0; nt < 8; nt++) {
                const uint32_t* bp = &Bs[(kb + tig) * BS_STRIDE + wn + nt * 8 + gid];
                bf[nt][0] = bp[0];
                bf[nt][1] = bp[4 * BS_STRIDE];
            }
#pragma unroll
            for (int mt = 0; mt < 2; mt++)
#pragma unroll
                for (int nt = 0; nt < 8; nt++) {
                    asm volatile(
                        "mma.sync.aligned.m16n8k8.row.col.f32.tf32.tf32.f32 "
                        "{%0,%1,%2,%3}, {%4,%5,%6,%7}, {%8,%9}, {%0,%1,%2,%3};"
                        : "+f"(acc[mt][nt][0]), "+f"(acc[mt][nt][1]),
                          "+f"(acc[mt][nt][2]), "+f"(acc[mt][nt][3])
                        : "r"(af[mt][0]), "r"(af[mt][1]), "r"(af[mt][2]), "r"(af[mt][3]),
                          "r"(bf[nt][0]), "r"(bf[nt][1]));
                }
        }
        __syncthreads();
    }
#pragma unroll
    for (int mt = 0; mt < 2; mt++)
#pragma unroll
        for (int nt = 0; nt < 8; nt++) {
            int row = m0 + wm + mt * 16 + gid;
            int col = n0 + wn + nt * 8 + tig * 2;
            *(float2*)&Co[(size_t)row * Cc + col] = make_float2(acc[mt][nt][0], acc[mt][nt][1]);
            *(float2*)&Co[(size_t)(row + 8) * Cc + col] = make_float2(acc[mt][nt][2], acc[mt][nt][3]);
        }
}

__global__ __launch_bounds__(256) void k_gemm_qkv(const float* __restrict__ Wq,
                                                  const float* __restrict__ Wk,
                                                  const float* __restrict__ Wv) {
    const float* A = (blockIdx.z == 0) ? s_xq : (blockIdx.z == 1) ? s_xk : s_xv;
    const float* W = (blockIdx.z == 0) ? Wq : (blockIdx.z == 1) ? Wk : Wv;
    float* Co = (blockIdx.z == 0) ? s_rq : (blockIdx.z == 1) ? s_rk : s_rv;
    gemm_tf32<false>(A, W, Co, nullptr, nullptr, nullptr, nullptr);
}

__global__ __launch_bounds__(256) void k_gemm_out(const float* __restrict__ Wo,
                                                  const float* __restrict__ gx,
                                                  const float* __restrict__ bx,
                                                  float* __restrict__ out) {
    gemm_tf32<true>(s_o, Wo, out, s_mu, s_rs, gx, bx);
}

// ---------------- K-lnstats: per-row mean/rstd of s_o ----------------
__global__ __launch_bounds__(256) void k_lnstats() {
    int row = blockIdx.x * 8 + (threadIdx.x >> 5);
    int lane = threadIdx.x & 31;
    const float* p = s_o + (size_t)row * Cc;
    float s = 0.f, q = 0.f;
    for (int c = lane * 4; c < Cc; c += 128) {
        float4 v = *(const float4*)(p + c);
        s += v.x + v.y + v.z + v.w;
        q += v.x * v.x + v.y * v.y + v.z * v.z + v.w * v.w;
    }
#pragma unroll
    for (int o = 16; o; o >>= 1) {
        s += __shfl_xor_sync(0xffffffffu, s, o);
        q += __shfl_xor_sync(0xffffffffu, q, o);
    }
    if (lane == 0) {
        float mu = s * (1.f / Cc);
        float var = q * (1.f / Cc) - mu * mu;
        s_mu[row] = mu;
        s_rs[row] = rsqrtf(var + 1e-5f);
    }
}

// ---------------- K5: LayerNorm (+RoPE for q,k), write (B,H,T,D) ----------
__global__ __launch_bounds__(256) void k_lnrope(const float* __restrict__ gr, const float* __restrict__ br,
                                                const float* __restrict__ gk, const float* __restrict__ bk,
                                                const float* __restrict__ gv, const float* __restrict__ bv,
                                                const float* __restrict__ cosp, const float* __restrict__ sinp) {
    int mode = blockIdx.y;
    const float* raw = (mode == 0) ? s_rq : (mode == 1) ? s_rk : s_rv;
    float* outp = (mode == 0) ? s_q : (mode == 1) ? s_k : s_v;
    const float* gp = (mode == 0) ? gr : (mode == 1) ? gk : gv;
    const float* bp = (mode == 0) ? br : (mode == 1) ? bk : bv;
    int bt = blockIdx.x;
    int t = bt & (Tt - 1);
    int b = bt >> 10;
    __shared__ float srow[Cc];
    __shared__ float red[16];
    float ls = 0.f, lq = 0.f;
    for (int c = threadIdx.x; c < Cc; c += 256) {
        float v = raw[(size_t)bt * Cc + c];
        srow[c] = v;
        ls += v;
        lq += v * v;
    }
#pragma unroll
    for (int o = 16; o; o >>= 1) {
        ls += __shfl_xor_sync(0xffffffffu, ls, o);
        lq += __shfl_xor_sync(0xffffffffu, lq, o);
    }
    if ((threadIdx.x & 31) == 0) {
        red[threadIdx.x >> 5] = ls;
        red[8 + (threadIdx.x >> 5)] = lq;
    }
    __syncthreads();
    float sum = 0.f, sq = 0.f;
#pragma unroll
    for (int i = 0; i < 8; i++) {
        sum += red[i];
        sq += red[8 + i];
    }
    float mu = sum * (1.f / Cc);
    float var = sq * (1.f / Cc) - mu * mu;
    float rstd = rsqrtf(var + 1e-5f);
    for (int c = threadIdx.x; c < Cc; c += 256)
        srow[c] = (srow[c] - mu) * rstd * gp[c] + bp[c];
    __syncthreads();
    for (int c = threadIdx.x; c < Cc; c += 256) {
        int hh = c >> 6, d = c & 63;
        float y;
        if (mode < 2) {
            if (d < 32)
                y = srow[c] * cosp[t * 32 + d] - srow[c + 32] * sinp[t * 32 + d];
            else
                y = srow[c - 32] * sinp[t * 32 + d - 32] + srow[c] * cosp[t * 32 + d - 32];
        } else {
            y = srow[c];
        }
        outp[((size_t)(b * Hh + hh) * Tt + t) * Dd + d] = y;
    }
}

// ---------------- K6: tensor-core causal flash attention ------------------
#define SD 68
#define SDV 72
#define FL_TILE (64 * SD)
#define FL_SMEM ((5 * FL_TILE + 64 * SDV + 256) * 4)

__global__ __launch_bounds__(256) void k_flash() {
    extern __shared__ uint32_t fsm[];
    uint32_t* Qh = fsm;
    uint32_t* Ql = Qh + FL_TILE;
    uint32_t* Kh = Ql + FL_TILE;
    uint32_t* Kl = Kh + FL_TILE;
    uint32_t* Pt = Kl + FL_TILE;
    uint32_t* Vt = Pt + FL_TILE;
    float* red = (float*)(Vt + 64 * SDV);

    int tid = threadIdx.x;
    int warp = tid >> 5, lane = tid & 31;
    int gid = lane >> 2, tig = lane & 3;
    int qw = (warp & 3) * 16;
    int sh = warp >> 2;
    int sb = sh * 32;

    int q0 = blockIdx.x * 64;
    int bh = blockIdx.y;
    int b = bh >> 5, h = bh & 31;
    const float* qp = s_q + (size_t)bh * Tt * Dd;
    const float* kp = s_k + (size_t)bh * Tt * Dd;
    const float* vp = s_v + (size_t)bh * Tt * Dd;

#pragma unroll
    for (int it = 0; it < 4; it++) {
        int lin = tid + it * 256;
        int row = lin >> 4, c4 = (lin & 15) * 4;
        float4 v = *(const float4*)(qp + (size_t)(q0 + row) * 64 + c4);
        v.x *= 0.125f; v.y *= 0.125f; v.z *= 0.125f; v.w *= 0.125f;
        uint4 hi = make_uint4(f2tf(v.x), f2tf(v.y), f2tf(v.z), f2tf(v.w));
        uint4 lo = make_uint4(f2tf(v.x - __uint_as_float(hi.x)),
                              f2tf(v.y - __uint_as_float(hi.y)),
                              f2tf(v.z - __uint_as_float(hi.z)),
                              f2tf(v.w - __uint_as_float(hi.w)));
        *(uint4*)&Qh[row * SD + c4] = hi;
        *(uint4*)&Ql[row * SD + c4] = lo;
    }

    float oacc[4][4];
#pragma unroll
    for (int nt = 0; nt < 4; nt++)
#pragma unroll
        for (int i = 0; i < 4; i++) oacc[nt][i] = 0.f;
    float m0 = NEG_INF, m1 = NEG_INF, l0 = 0.f, l1 = 0.f;
    int row0 = q0 + qw + gid;
    int row1 = row0 + 8;

    for (int s0 = 0; s0 <= q0; s0 += 64) {
        __syncthreads();
#pragma unroll
        for (int it = 0; it < 4; it++) {
            int lin = tid + it * 256;
            int row = lin >> 4, c4 = (lin & 15) * 4;
            float4 kv = *(const float4*)(kp + (size_t)(s0 + row) * 64 + c4);
            uint4 hi = make_uint4(f2tf(kv.x), f2tf(kv.y), f2tf(kv.z), f2tf(kv.w));
            uint4 lo = make_uint4(f2tf(kv.x - __uint_as_float(hi.x)),
                                  f2tf(kv.y - __uint_as_float(hi.y)),
                                  f2tf(kv.z - __uint_as_float(hi.z)),
                                  f2tf(kv.w - __uint_as_float(hi.w)));
            *(uint4*)&Kh[row * SD + c4] = hi;
            *(uint4*)&Kl[row * SD + c4] = lo;
            float4 vv = *(const float4*)(vp + (size_t)(s0 + row) * 64 + c4);
            uint4 vt = make_uint4(f2tf(vv.x), f2tf(vv.y), f2tf(vv.z), f2tf(vv.w));
            *(uint4*)&Vt[row * SDV + c4] = vt;
        }
        __syncthreads();

        float sacc[4][4];
#pragma unroll
        for (int nt = 0; nt < 4; nt++)
#pragma unroll
            for (int i = 0; i < 4; i++) sacc[nt][i] = 0.f;
#pragma unroll
        for (int kk = 0; kk < 8; kk++) {
            int kb = kk * 8;
            uint32_t ah[4], al[4];
            const uint32_t* aph = &Qh[(qw + gid) * SD + kb + tig];
            const uint32_t* apl = &Ql[(qw + gid) * SD + kb + tig];
            ah[0] = aph[0]; ah[1] = aph[8 * SD]; ah[2] = aph[4]; ah[3] = aph[8 * SD + 4];
            al[0] = apl[0]; al[1] = apl[8 * SD]; al[2] = apl[4]; al[3] = apl[8 * SD + 4];
#pragma unroll
            for (int nt = 0; nt < 4; nt++) {
                int n0 = sb + nt * 8;
                const uint32_t* bph = &Kh[(n0 + gid) * SD + kb + tig];
                const uint32_t* bpl = &Kl[(n0 + gid) * SD + kb + tig];
                uint32_t bh0 = bph[0], bh1 = bph[4];
                uint32_t bl0 = bpl[0], bl1 = bpl[4];
#define MMA_S(Areg, B0, B1)                                                   \
    asm volatile(                                                             \
        "mma.sync.aligned.m16n8k8.row.col.f32.tf32.tf32.f32 "                 \
        "{%0,%1,%2,%3}, {%4,%5,%6,%7}, {%8,%9}, {%0,%1,%2,%3};"               \
        : "+f"(sacc[nt][0]), "+f"(sacc[nt][1]), "+f"(sacc[nt][2]),            \
          "+f"(sacc[nt][3])                                                   \
        : "r"(Areg[0]), "r"(Areg[1]), "r"(Areg[2]), "r"(Areg[3]), "r"(B0),    \
          "r"(B1));
                MMA_S(ah, bh0, bh1)
                MMA_S(ah, bl0, bl1)
                MMA_S(al, bh0, bh1)
#undef MMA_S
            }
        }

        float mt0 = NEG_INF, mt1 = NEG_INF;
#pragma unroll
        for (int nt = 0; nt < 4; nt++) {
            int cbase = s0 + sb + nt * 8 + 2 * tig;
            sacc[nt][0] = (cbase <= row0) ? sacc[nt][0] : NEG_INF;
            sacc[nt][1] = (cbase + 1 <= row0) ? sacc[nt][1] : NEG_INF;
            sacc[nt][2] = (cbase <= row1) ? sacc[nt][2] : NEG_INF;
            sacc[nt][3] = (cbase + 1 <= row1) ? sacc[nt][3] : NEG_INF;
            mt0 = fmaxf(mt0, fmaxf(sacc[nt][0], sacc[nt][1]));
            mt1 = fmaxf(mt1, fmaxf(sacc[nt][2], sacc[nt][3]));
        }
        mt0 = fmaxf(mt0, __shfl_xor_sync(0xffffffffu, mt0, 1));
        mt0 = fmaxf(mt0, __shfl_xor_sync(0xffffffffu, mt0, 2));
        mt1 = fmaxf(mt1, __shfl_xor_sync(0xffffffffu, mt1, 1));
        mt1 = fmaxf(mt1, __shfl_xor_sync(0xffffffffu, mt1, 2));
        if (tig == 0) {
            red[sh * 64 + qw + gid] = mt0;
            red[sh * 64 + qw + gid + 8] = mt1;
        }
        __syncthreads();
        float mn0 = fmaxf(m0, fmaxf(red[qw + gid], red[64 + qw + gid]));
        float mn1 = fmaxf(m1, fmaxf(red[qw + gid + 8], red[64 + qw + gid + 8]));
        float corr0 = __expf(m0 - mn0);
        float corr1 = __expf(m1 - mn1);
        m0 = mn0; m1 = mn1;

        float ls0 = 0.f, ls1 = 0.f;
#pragma unroll
        for (int nt = 0; nt < 4; nt++) {
            int cb = sb + nt * 8 + 2 * tig;
            float p0 = __expf(sacc[nt][0] - mn0);
            float p1 = __expf(sacc[nt][1] - mn0);
            float p2 = __expf(sacc[nt][2] - mn1);
            float p3 = __expf(sacc[nt][3] - mn1);
            ls0 += p0 + p1;
            ls1 += p2 + p3;
            Pt[(qw + gid) * SD + cb] = f2tf(p0);
            Pt[(qw + gid) * SD + cb + 1] = f2tf(p1);
            Pt[(qw + gid + 8) * SD + cb] = f2tf(p2);
            Pt[(qw + gid + 8) * SD + cb + 1] = f2tf(p3);
        }
        ls0 += __shfl_xor_sync(0xffffffffu, ls0, 1);
        ls0 += __shfl_xor_sync(0xffffffffu, ls0, 2);
        ls1 += __shfl_xor_sync(0xffffffffu, ls1, 1);
        ls1 += __shfl_xor_sync(0xffffffffu, ls1, 2);
        if (tig == 0) {
            red[128 + sh * 64 + qw + gid] = ls0;
            red[128 + sh * 64 + qw + gid + 8] = ls1;
        }
        __syncthreads();
        l0 = l0 * corr0 + red[128 + qw + gid] + red[128 + 64 + qw + gid];
        l1 = l1 * corr1 + red[128 + qw + gid + 8] + red[128 + 64 + qw + gid + 8];

#pragma unroll
        for (int nt = 0; nt < 4; nt++) {
            oacc[nt][0] *= corr0;
            oacc[nt][1] *= corr0;
            oacc[nt][2] *= corr1;
            oacc[nt][3] *= corr1;
        }
#pragma unroll
        for (int kk = 0; kk < 8; kk++) {
            int kb = kk * 8;
            uint32_t af[4];
            const uint32_t* ap = &Pt[(qw + gid) * SD + kb + tig];
            af[0] = ap[0]; af[1] = ap[8 * SD]; af[2] = ap[4]; af[3] = ap[8 * SD + 4];
#pragma unroll
            for (int nt = 0; nt < 4; nt++) {
                int n0 = sb + nt * 8;
                uint32_t b0 = Vt[(kb + tig) * SDV + n0 + gid];
                uint32_t b1 = Vt[(kb + tig + 4) * SDV + n0 + gid];
                asm volatile(
                    "mma.sync.aligned.m16n8k8.row.col.f32.tf32.tf32.f32 "
                    "{%0,%1,%2,%3}, {%4,%5,%6,%7}, {%8,%9}, {%0,%1,%2,%3};"
                    : "+f"(oacc[nt][0]), "+f"(oacc[nt][1]), "+f"(oacc[nt][2]),
                      "+f"(oacc[nt][3])
                    : "r"(af[0]), "r"(af[1]), "r"(af[2]), "r"(af[3]),
                      "r"(b0), "r"(b1));
            }
        }
    }

    float inv0 = 1.f / l0, inv1 = 1.f / l1;
#pragma unroll
    for (int nt = 0; nt < 4; nt++) {
        int col = h * 64 + sb + nt * 8 + 2 * tig;
        *(float2*)&s_o[(size_t)(b * Tt + row0) * Cc + col] =
            make_float2(oacc[nt][0] * inv0, oacc[nt][1] * inv0);
        *(float2*)&s_o[(size_t)(b * Tt + row1) * Cc + col] =
            make_float2(oacc[nt][2] * inv1, oacc[nt][3] * inv1);
    }
}

// ---------------- launch ----------------
extern "C" void kernel_launch(void* const* d_in, const int* in_sizes, int n_in,
                              void* d_out, int out_size) {
    const float* x = (const float*)d_in[0];
    const float* shift = (const float*)d_in[1];
    const float* tmx = (const float*)d_in[2];
    const float* tmr = (const float*)d_in[3];
    const float* tmk = (const float*)d_in[4];
    const float* tmv = (const float*)d_in[5];
    const float* w1 = (const float*)d_in[6];
    const float* w2 = (const float*)d_in[7];
    const float* Wq = (const float*)d_in[8];
    const float* Wk = (const float*)d_in[9];
    const float* Wv = (const float*)d_in[10];
    const float* Wo = (const float*)d_in[11];
    const float* gr = (const float*)d_in[12];
    const float* br = (const float*)d_in[13];
    const float* gk = (const float*)d_in[14];
    const float* bk = (const float*)d_in[15];
    const float* gv = (const float*)d_in[16];
    const float* bv = (const float*)d_in[17];
    const float* gx = (const float*)d_in[18];
    const float* bx = (const float*)d_in[19];
    const float* cosp = (const float*)d_in[20];
    const float* sinp = (const float*)d_in[21];
    float* out = (float*)d_out;

    cudaFuncSetAttribute(k_premix, cudaFuncAttributeMaxDynamicSharedMemorySize, PM_SMEM);
    cudaFuncSetAttribute(k_flash, cudaFuncAttributeMaxDynamicSharedMemorySize, FL_SMEM);

    k_premix<<<BT / PM_ROWS, 256, PM_SMEM>>>(x, shift, tmx, tmr, tmk, tmv, w1, w2);
    k_gemm_qkv<<<dim3(16, 16, 3), 256>>>(Wq, Wk, Wv);
    k_lnrope<<<dim3(BT, 3), 256>>>(gr, br, gk, bk, gv, bv, cosp, sinp);
    k_flash<<<dim3(16, 64), 256, FL_SMEM>>>();
    k_lnstats<<<BT / 8, 256>>>();
    k_gemm_out<<<dim3(16, 16), 256>>>(Wo, gx, bx, out);
}